// round 14
// baseline (speedup 1.0000x reference)
#include <cuda_runtime.h>

// Problem constants
#define NB      2
#define L_SEQ   2048
#define D_MODEL 1024
#define NH      16
#define HDIM    64
#define ROWSTR  (3 * D_MODEL)   // 3072, row stride of qkv buffer

// Scratch (allocation-free rule: __device__ globals)
__device__ float g_qkv[(size_t)NB * L_SEQ * 3 * D_MODEL]; // 48 MB
__device__ float g_att[(size_t)NB * L_SEQ * D_MODEL];     // 16 MB

// ---------------------------------------------------------------------------
// Packed fp32x2 helpers (sm_100+ PTX; ptxas never emits these from C++).
// Numerically identical to scalar FFMA (IEEE fp32 fused per half).
// Packed layout (lo = lower address) matches float memory order, so packed
// accumulators can be stored to global directly without unpacking.
// ---------------------------------------------------------------------------
__device__ __forceinline__ unsigned long long dup2(float v) {
    unsigned long long r;
    asm("mov.b64 %0, {%1, %1};" : "=l"(r) : "r"(__float_as_uint(v)));
    return r;
}
__device__ __forceinline__ void unpack2(unsigned long long p, float& lo, float& hi) {
    unsigned int a, b;
    asm("mov.b64 {%0, %1}, %2;" : "=r"(a), "=r"(b) : "l"(p));
    lo = __uint_as_float(a);
    hi = __uint_as_float(b);
}
__device__ __forceinline__ unsigned long long fma2(unsigned long long a,
                                                   unsigned long long b,
                                                   unsigned long long c) {
    unsigned long long d;
    asm("fma.rn.f32x2 %0, %1, %2, %3;" : "=l"(d) : "l"(a), "l"(b), "l"(c));
    return d;
}
__device__ __forceinline__ unsigned long long mul2(unsigned long long a,
                                                   unsigned long long b) {
    unsigned long long d;
    asm("mul.rn.f32x2 %0, %1, %2;" : "=l"(d) : "l"(a), "l"(b));
    return d;
}
// Raw hardware exp2 (MUFU.EX2) -- scores live in log2 domain.
__device__ __forceinline__ float ex2(float x) {
    float y;
    asm("ex2.approx.ftz.f32 %0, %1;" : "=f"(y) : "f"(x));
    return y;
}
// Fast reciprocal (MUFU.RCP, <=1 ulp) for the epilogue normalization.
__device__ __forceinline__ float frcp(float x) {
    float y;
    asm("rcp.approx.ftz.f32 %0, %1;" : "=f"(y) : "f"(x));
    return y;
}

// ---------------------------------------------------------------------------
// GEMM-NT: C[m,n] = sum_k A[m*K+k] * B[n*K+k]
// BM=BN=128, BK=16, 256 threads, 8x8 microtile (packed f32x2 along n).
// Double-buffered smem, register prefetch, ONE __syncthreads per K-tile.
// The staging STS sits BETWEEN kk=11 and kk=12 of the compute loop: the
// first 12 kk shadow the prefetch LDG (~768 cyc >= DRAM), the last 4 kk
// (~256 cyc fma) absorb the STS issue + BAR store-drain.
// ---------------------------------------------------------------------------
#define GBK    16
#define GSPLIT 12
#define GPAD   132
#define GEMM_SMEM (2 * 2 * GBK * GPAD * (int)sizeof(float))   // 67584 B

__global__ __launch_bounds__(256, 2) void gemm_nt_kernel(
    const float* __restrict__ A, const float* __restrict__ B,
    float* __restrict__ C, int M, int N, int K)
{
    extern __shared__ float gsm[];
    float* Asm = gsm;                        // [2][GBK][GPAD]
    float* Bsm = gsm + 2 * GBK * GPAD;       // [2][GBK][GPAD]

    const int tid = threadIdx.x;
    const int tx = tid & 15;
    const int ty = tid >> 4;
    const int bm = blockIdx.y * 128;
    const int bn = blockIdx.x * 128;

    const int lc = tid & 15;          // k within tile
    const int lr = (tid >> 4) * 4;    // row base

    // loop-carried base pointers (advance by GBK per tile)
    const float* Ap[2];
    const float* Bp[2];
#pragma unroll
    for (int half = 0; half < 2; half++) {
        Ap[half] = A + (size_t)(bm + lr + half * 64) * K + lc;
        Bp[half] = B + (size_t)(bn + lr + half * 64) * K + lc;
    }

    float ra[2][4], rb[2][4];

    // prefetch tile 0 into registers
#pragma unroll
    for (int half = 0; half < 2; half++)
#pragma unroll
        for (int i = 0; i < 4; i++) {
            ra[half][i] = Ap[half][i * K];
            rb[half][i] = Bp[half][i * K];
        }
    // store to buffer 0
#pragma unroll
    for (int half = 0; half < 2; half++) {
        int r = lr + half * 64;
        *(float4*)&Asm[(0 * GBK + lc) * GPAD + r] =
            make_float4(ra[half][0], ra[half][1], ra[half][2], ra[half][3]);
        *(float4*)&Bsm[(0 * GBK + lc) * GPAD + r] =
            make_float4(rb[half][0], rb[half][1], rb[half][2], rb[half][3]);
    }
    __syncthreads();

    // packed accumulators: acc2[i][j2] = columns (tx*8 + 2*j2, +1)
    unsigned long long acc2[8][4];
#pragma unroll
    for (int i = 0; i < 8; i++)
#pragma unroll
        for (int j = 0; j < 4; j++) acc2[i][j] = 0ULL;

    int cur = 0;
    for (int k0 = 0; k0 < K; k0 += GBK) {
        const bool has_next = (k0 + GBK) < K;

        // prefetch next tile into registers (shadow: first GSPLIT kk below)
        if (has_next) {
#pragma unroll
            for (int half = 0; half < 2; half++) {
                Ap[half] += GBK;
                Bp[half] += GBK;
#pragma unroll
                for (int i = 0; i < 4; i++) {
                    ra[half][i] = Ap[half][i * K];
                    rb[half][i] = Bp[half][i * K];
                }
            }
        }

        const float* Ac = &Asm[cur * GBK * GPAD];
        const float* Bc = &Bsm[cur * GBK * GPAD];

        // compute kk = 0 .. GSPLIT-1 (packed f32x2)
#pragma unroll
        for (int kk = 0; kk < GSPLIT; kk++) {
            float a[8];
            *(float4*)&a[0] = *(const float4*)&Ac[kk * GPAD + ty * 8];
            *(float4*)&a[4] = *(const float4*)&Ac[kk * GPAD + ty * 8 + 4];
            ulonglong2 b01 = *(const ulonglong2*)&Bc[kk * GPAD + tx * 8];
            ulonglong2 b23 = *(const ulonglong2*)&Bc[kk * GPAD + tx * 8 + 4];
            unsigned long long b2[4] = {b01.x, b01.y, b23.x, b23.y};
#pragma unroll
            for (int i = 0; i < 8; i++) {
                unsigned long long a2 = dup2(a[i]);   // alu pipe, dual-issues
#pragma unroll
                for (int j = 0; j < 4; j++)
                    acc2[i][j] = fma2(a2, b2[j], acc2[i][j]);
            }
        }

        // stage next tile mid-loop: remaining kk absorb STS + barrier drain
        if (has_next) {
            int nxt = cur ^ 1;
#pragma unroll
            for (int half = 0; half < 2; half++) {
                int r = lr + half * 64;
                *(float4*)&Asm[(nxt * GBK + lc) * GPAD + r] =
                    make_float4(ra[half][0], ra[half][1], ra[half][2], ra[half][3]);
                *(float4*)&Bsm[(nxt * GBK + lc) * GPAD + r] =
                    make_float4(rb[half][0], rb[half][1], rb[half][2], rb[half][3]);
            }
        }

        // compute kk = GSPLIT .. GBK-1
#pragma unroll
        for (int kk = GSPLIT; kk < GBK; kk++) {
            float a[8];
            *(float4*)&a[0] = *(const float4*)&Ac[kk * GPAD + ty * 8];
            *(float4*)&a[4] = *(const float4*)&Ac[kk * GPAD + ty * 8 + 4];
            ulonglong2 b01 = *(const ulonglong2*)&Bc[kk * GPAD + tx * 8];
            ulonglong2 b23 = *(const ulonglong2*)&Bc[kk * GPAD + tx * 8 + 4];
            unsigned long long b2[4] = {b01.x, b01.y, b23.x, b23.y};
#pragma unroll
            for (int i = 0; i < 8; i++) {
                unsigned long long a2 = dup2(a[i]);
#pragma unroll
                for (int j = 0; j < 4; j++)
                    acc2[i][j] = fma2(a2, b2[j], acc2[i][j]);
            }
        }

        __syncthreads();
        cur ^= 1;
    }

    // epilogue: packed pairs are already in float memory order -> store direct
#pragma unroll
    for (int i = 0; i < 8; i++) {
        size_t base = (size_t)(bm + ty * 8 + i) * N + bn + tx * 8;
        ulonglong2 lo, hi;
        lo.x = acc2[i][0]; lo.y = acc2[i][1];
        hi.x = acc2[i][2]; hi.y = acc2[i][3];
        *(ulonglong2*)&C[base]     = lo;
        *(ulonglong2*)&C[base + 4] = hi;
    }
}

// ---------------------------------------------------------------------------
// Flash attention (causal, fp32, packed f32x2, log2-domain softmax).
// BQ=BK=64, hd=64, 256 threads, 4x4 microtile.
// GRID ORDER (LPT): gridDim.x = b*h (32), gridDim.y = q-blocks (32) with
// blockIdx.y REVERSED -> linear bid order enumerates the heaviest q-rows
// across ALL heads first. Wave 1 (296 CTAs) = the ~10 heaviest q-rows;
// lighter CTAs backfill -> near-optimal makespan (LPT), short tail wave.
// K/V smem DOUBLE-BUFFERED, ONE __syncthreads per k-tile; staging STS and
// Ss STS hoisted so compute absorbs their latency. Packed epilogues.
// ---------------------------------------------------------------------------
#define FPITCH 68
#define FTILE  (64 * FPITCH)                                  // 4352 floats
#define FLASH_SMEM (6 * FTILE * (int)sizeof(float))           // 104448 B
// (1/sqrt(64)) * log2(e) = 0.125 * 1.4426950408889634
#define QSCALE 0.18033688011111793f
#define TILESTEP (64 * ROWSTR)

__global__ __launch_bounds__(256, 2) void flash_attn_kernel(
    const float* __restrict__ qkv, float* __restrict__ outp)
{
    extern __shared__ float sm[];
    float* Qt = sm;                              // [64 hd][68] transposed, prescaled
    // buf b: Kt = sm + (1+2b)*FTILE, Vs = sm + (2+2b)*FTILE
    float* Ss = sm + 5 * FTILE;                  // [64 q][68] probabilities

    const int tid = threadIdx.x;
    const int tx = tid & 15;
    const int ty = tid >> 4;
    // LPT order: x = (b,h); y = q-block, reversed so heavy rows launch first
    const int q0 = (gridDim.y - 1 - blockIdx.y) * 64;
    const int b  = blockIdx.x >> 4;
    const int h  = blockIdx.x & 15;

    const size_t seqbase = (size_t)b * L_SEQ * ROWSTR;

    const int c  = tid & 63;          // hd column for K/Q transpose loads
    const int r4 = (tid >> 6) * 4;    // row base
    const int vr = ty;                // V row base
    const int vc = tx * 4;            // V col base

    // loop-carried per-thread base pointers (advance by TILESTEP per tile)
    const float* Qp = qkv + seqbase + h * HDIM + c + (size_t)q0 * ROWSTR;
    const float* Kp = qkv + seqbase + D_MODEL + h * HDIM + c;
    const float* Vp = qkv + seqbase + 2 * D_MODEL + h * HDIM + vc;
    // 32-bit row offsets (max 2048*3072 < 2^31)
    int koff[4], voff[4];
#pragma unroll
    for (int it = 0; it < 4; it++) {
        koff[it] = (r4 + it * 16) * ROWSTR;
        voff[it] = (vr + it * 16) * ROWSTR;
    }

    const int n_tiles = q0 / 64 + 1;

    float kreg[4][4];
    float4 vreg[4];

    // ---- prologue: Q (prescaled to log2 domain) + first K/V tile ----
#pragma unroll
    for (int it = 0; it < 4; it++) {
        int r = r4 + it * 16;
        float t0 = Qp[koff[it] + 0 * ROWSTR] * QSCALE;
        float t1 = Qp[koff[it] + 1 * ROWSTR] * QSCALE;
        float t2 = Qp[koff[it] + 2 * ROWSTR] * QSCALE;
        float t3 = Qp[koff[it] + 3 * ROWSTR] * QSCALE;
        *(float4*)&Qt[c * FPITCH + r] = make_float4(t0, t1, t2, t3);
    }
#pragma unroll
    for (int it = 0; it < 4; it++) {
        kreg[it][0] = Kp[koff[it] + 0 * ROWSTR];
        kreg[it][1] = Kp[koff[it] + 1 * ROWSTR];
        kreg[it][2] = Kp[koff[it] + 2 * ROWSTR];
        kreg[it][3] = Kp[koff[it] + 3 * ROWSTR];
    }
#pragma unroll
    for (int it = 0; it < 4; it++)
        vreg[it] = *(const float4*)&Vp[voff[it]];

    {
        float* Kt0 = sm + 1 * FTILE;
        float* Vs0 = sm + 2 * FTILE;
#pragma unroll
        for (int it = 0; it < 4; it++) {
            int r = r4 + it * 16;
            *(float4*)&Kt0[c * FPITCH + r] =
                make_float4(kreg[it][0], kreg[it][1], kreg[it][2], kreg[it][3]);
        }
#pragma unroll
        for (int it = 0; it < 4; it++)
            *(float4*)&Vs0[(vr + it * 16) * FPITCH + vc] = vreg[it];
    }
    __syncthreads();

    // packed accumulators: acc2[i][j2] = hd cols (tx*4 + 2*j2, +1)
    unsigned long long acc2[4][2];
    float m_i[4], l_i[4];
#pragma unroll
    for (int i = 0; i < 4; i++) {
        m_i[i] = -1e30f;
        l_i[i] = 0.0f;
        acc2[i][0] = 0ULL;
        acc2[i][1] = 0ULL;
    }

    int cur = 0;
    for (int t = 0; t < n_tiles; t++) {
        const bool has_next = (t + 1) < n_tiles;
        const float* Kt = sm + (1 + 2 * cur) * FTILE;
        const float* Vs = sm + (2 + 2 * cur) * FTILE;

        // prefetch NEXT K/V tile into registers (shadow: S-loop + softmax)
        if (has_next) {
            Kp += TILESTEP;
            Vp += TILESTEP;
#pragma unroll
            for (int it = 0; it < 4; it++) {
                kreg[it][0] = Kp[koff[it] + 0 * ROWSTR];
                kreg[it][1] = Kp[koff[it] + 1 * ROWSTR];
                kreg[it][2] = Kp[koff[it] + 2 * ROWSTR];
                kreg[it][3] = Kp[koff[it] + 3 * ROWSTR];
            }
#pragma unroll
            for (int it = 0; it < 4; it++)
                vreg[it] = *(const float4*)&Vp[voff[it]];
        }

        // S = (Q*scale*log2e) K^T  -- packed along k-columns (tx*4 pairs)
        unsigned long long s2[4][2];
#pragma unroll
        for (int i = 0; i < 4; i++) { s2[i][0] = 0ULL; s2[i][1] = 0ULL; }

#pragma unroll
        for (int kk = 0; kk < 64; kk++) {
            float av[4];
            *(float4*)av = *(const float4*)&Qt[kk * FPITCH + ty * 4];
            ulonglong2 kb = *(const ulonglong2*)&Kt[kk * FPITCH + tx * 4];
#pragma unroll
            for (int i = 0; i < 4; i++) {
                unsigned long long a2 = dup2(av[i]);
                s2[i][0] = fma2(a2, kb.x, s2[i][0]);
                s2[i][1] = fma2(a2, kb.y, s2[i][1]);
            }
        }

        // unpack S for masking/softmax
        float s[4][4];
#pragma unroll
        for (int i = 0; i < 4; i++) {
            unpack2(s2[i][0], s[i][0], s[i][1]);
            unpack2(s2[i][1], s[i][2], s[i][3]);
        }

        // causal mask on the diagonal tile (last tile: k0 == q0)
        if (!has_next) {
#pragma unroll
            for (int i = 0; i < 4; i++) {
                int qi = ty * 4 + i;
#pragma unroll
                for (int j = 0; j < 4; j++) {
                    int kj = tx * 4 + j;
                    if (kj > qi) s[i][j] = -1e30f;
                }
            }
        }

        // ---- online softmax, log2 domain, STAGE-MAJOR (4 rows interleaved) --
        float mx[4], rs[4], mnew[4], sf[4];
#pragma unroll
        for (int i = 0; i < 4; i++)
            mx[i] = fmaxf(fmaxf(s[i][0], s[i][1]), fmaxf(s[i][2], s[i][3]));
#pragma unroll
        for (int off = 8; off >= 1; off >>= 1)
#pragma unroll
            for (int i = 0; i < 4; i++)
                mx[i] = fmaxf(mx[i], __shfl_xor_sync(0xffffffffu, mx[i], off, 16));
#pragma unroll
        for (int i = 0; i < 4; i++) {
            mnew[i] = fmaxf(m_i[i], mx[i]);
            sf[i]   = ex2(m_i[i] - mnew[i]);
        }
#pragma unroll
        for (int i = 0; i < 4; i++) {
            s[i][0] = ex2(s[i][0] - mnew[i]);
            s[i][1] = ex2(s[i][1] - mnew[i]);
            s[i][2] = ex2(s[i][2] - mnew[i]);
            s[i][3] = ex2(s[i][3] - mnew[i]);
            rs[i] = (s[i][0] + s[i][1]) + (s[i][2] + s[i][3]);
        }

        // Ss STS hoisted: s[] is final; store NOW so the STS->LDS chain is
        // covered while the sum-shuffles and rescale proceed underneath.
#pragma unroll
        for (int i = 0; i < 4; i++)
            *(float4*)&Ss[(ty * 4 + i) * FPITCH + tx * 4] =
                make_float4(s[i][0], s[i][1], s[i][2], s[i][3]);

#pragma unroll
        for (int off = 8; off >= 1; off >>= 1)
#pragma unroll
            for (int i = 0; i < 4; i++)
                rs[i] += __shfl_xor_sync(0xffffffffu, rs[i], off, 16);
#pragma unroll
        for (int i = 0; i < 4; i++) {
            l_i[i] = l_i[i] * sf[i] + rs[i];
            m_i[i] = mnew[i];
            unsigned long long sf2 = dup2(sf[i]);
            acc2[i][0] = mul2(acc2[i][0], sf2);
            acc2[i][1] = mul2(acc2[i][1], sf2);
        }
        __syncwarp();

        // K/V staging STS hoisted BEFORE P.V: targets buf[nxt] (disjoint from
        // buf[cur] being read below); the P.V body absorbs the STS issue and
        // the BAR's store-drain instead of them landing on the tile tail.
        if (has_next) {
            int nxt = cur ^ 1;
            float* Ktn = sm + (1 + 2 * nxt) * FTILE;
            float* Vsn = sm + (2 + 2 * nxt) * FTILE;
#pragma unroll
            for (int it = 0; it < 4; it++) {
                int r = r4 + it * 16;
                *(float4*)&Ktn[c * FPITCH + r] =
                    make_float4(kreg[it][0], kreg[it][1], kreg[it][2], kreg[it][3]);
            }
#pragma unroll
            for (int it = 0; it < 4; it++)
                *(float4*)&Vsn[(vr + it * 16) * FPITCH + vc] = vreg[it];
        }

        // O += P V  -- packed along hd columns
#pragma unroll
        for (int kk4 = 0; kk4 < 64; kk4 += 4) {
            float4 p[4];
#pragma unroll
            for (int i = 0; i < 4; i++)
                p[i] = *(const float4*)&Ss[(ty * 4 + i) * FPITCH + kk4];
#pragma unroll
            for (int u = 0; u < 4; u++) {
                ulonglong2 v2 = *(const ulonglong2*)&Vs[(kk4 + u) * FPITCH + tx * 4];
                float pe[4];
                pe[0] = (u == 0) ? p[0].x : (u == 1) ? p[0].y : (u == 2) ? p[0].z : p[0].w;
                pe[1] = (u == 0) ? p[1].x : (u == 1) ? p[1].y : (u == 2) ? p[1].z : p[1].w;
                pe[2] = (u == 0) ? p[2].x : (u == 1) ? p[2].y : (u == 2) ? p[2].z : p[2].w;
                pe[3] = (u == 0) ? p[3].x : (u == 1) ? p[3].y : (u == 2) ? p[3].z : p[3].w;
#pragma unroll
                for (int i = 0; i < 4; i++) {
                    unsigned long long pd = dup2(pe[i]);
                    acc2[i][0] = fma2(pd, v2.x, acc2[i][0]);
                    acc2[i][1] = fma2(pd, v2.y, acc2[i][1]);
                }
            }
        }

        // single barrier per tile: publishes buf[nxt] for iteration t+1
        if (has_next) {
            __syncthreads();
            cur ^= 1;
        }
    }

    // epilogue: O *= 1/l (packed), store packed pairs directly
#pragma unroll
    for (int i = 0; i < 4; i++) {
        unsigned long long inv2 = dup2(frcp(l_i[i]));
        ulonglong2 o;
        o.x = mul2(acc2[i][0], inv2);
        o.y = mul2(acc2[i][1], inv2);
        int q = q0 + ty * 4 + i;
        size_t base = (size_t)(b * L_SEQ + q) * D_MODEL + h * HDIM + tx * 4;
        *(ulonglong2*)&outp[base] = o;
    }
}

// ---------------------------------------------------------------------------
extern "C" void kernel_launch(void* const* d_in, const int* in_sizes, int n_in,
                              void* d_out, int out_size)
{
    const float* x     = (const float*)d_in[0];  // [2,2048,1024]
    const float* w_qkv = (const float*)d_in[1];  // [3072,1024]
    const float* w_out = (const float*)d_in[2];  // [1024,1024]
    float* out = (float*)d_out;                  // [2,2048,1024]

    float *qkv_buf = nullptr, *att_buf = nullptr;
    cudaGetSymbolAddress((void**)&qkv_buf, g_qkv);
    cudaGetSymbolAddress((void**)&att_buf, g_att);

    cudaFuncSetAttribute(gemm_nt_kernel,
                         cudaFuncAttributeMaxDynamicSharedMemorySize, GEMM_SMEM);
    cudaFuncSetAttribute(flash_attn_kernel,
                         cudaFuncAttributeMaxDynamicSharedMemorySize, FLASH_SMEM);

    const int M = NB * L_SEQ;   // 4096

    // 1) qkv = x @ w_qkv^T   [4096, 3072]
    gemm_nt_kernel<<<dim3(3 * D_MODEL / 128, M / 128), 256, GEMM_SMEM>>>(
        x, w_qkv, qkv_buf, M, 3 * D_MODEL, D_MODEL);

    // 2) causal flash attention -> g_att [4096, 1024]
    //    LPT grid: x = (b,h), y = q-blocks (reversed inside the kernel)
    flash_attn_kernel<<<dim3(NB * NH, L_SEQ / 64), 256, FLASH_SMEM>>>(
        qkv_buf, att_buf);

    // 3) out = att @ w_out^T  [4096, 1024]
    gemm_nt_kernel<<<dim3(D_MODEL / 128, M / 128), 256, GEMM_SMEM>>>(
        att_buf, w_out, out, M, D_MODEL, D_MODEL);
}

// round 17
// speedup vs baseline: 1.0008x; 1.0008x over previous
#include <cuda_runtime.h>

// Problem constants
#define NB      2
#define L_SEQ   2048
#define D_MODEL 1024
#define NH      16
#define HDIM    64
#define ROWSTR  (3 * D_MODEL)   // 3072, row stride of qkv buffer

// Scratch (allocation-free rule: __device__ globals)
__device__ float g_qkv[(size_t)NB * L_SEQ * 3 * D_MODEL]; // 48 MB
__device__ float g_att[(size_t)NB * L_SEQ * D_MODEL];     // 16 MB

// ---------------------------------------------------------------------------
// Packed fp32x2 helpers (sm_100+ PTX; ptxas never emits these from C++).
// ---------------------------------------------------------------------------
__device__ __forceinline__ unsigned long long dup2(float v) {
    unsigned long long r;
    asm("mov.b64 %0, {%1, %1};" : "=l"(r) : "r"(__float_as_uint(v)));
    return r;
}
__device__ __forceinline__ void unpack2(unsigned long long p, float& lo, float& hi) {
    unsigned int a, b;
    asm("mov.b64 {%0, %1}, %2;" : "=r"(a), "=r"(b) : "l"(p));
    lo = __uint_as_float(a);
    hi = __uint_as_float(b);
}
__device__ __forceinline__ unsigned long long fma2(unsigned long long a,
                                                   unsigned long long b,
                                                   unsigned long long c) {
    unsigned long long d;
    asm("fma.rn.f32x2 %0, %1, %2, %3;" : "=l"(d) : "l"(a), "l"(b), "l"(c));
    return d;
}
__device__ __forceinline__ unsigned long long mul2(unsigned long long a,
                                                   unsigned long long b) {
    unsigned long long d;
    asm("mul.rn.f32x2 %0, %1, %2;" : "=l"(d) : "l"(a), "l"(b));
    return d;
}
// Raw hardware exp2 (MUFU.EX2) -- scores live in log2 domain.
__device__ __forceinline__ float ex2(float x) {
    float y;
    asm("ex2.approx.ftz.f32 %0, %1;" : "=f"(y) : "f"(x));
    return y;
}
// Fast reciprocal (MUFU.RCP, <=1 ulp) for the epilogue normalization.
__device__ __forceinline__ float frcp(float x) {
    float y;
    asm("rcp.approx.ftz.f32 %0, %1;" : "=f"(y) : "f"(x));
    return y;
}

// ---------------------------------------------------------------------------
// GEMM-NT: C[m,n] = sum_k A[m*K+k] * B[n*K+k]
// BM=BN=128, BK=16, 256 threads, 8x8 microtile (packed f32x2 along n).
// SQUARE WARP FOOTPRINT: lanes remapped so each warp spans 8 tx x 4 ty
// (was 16x2). Per-kk LDS bytes/warp: 16*32(B)+2*32(A)=576B -> 8*32+4*32=
// 384B (-33%, 3 wavefronts of 128B). ncu R14 measured L1=76.9% as the
// binding resource (fma=54%); this attacks it directly. Same instructions,
// registers, smem layout; only the lane->(tx,ty) bijection changes.
// Double-buffered smem, mid-loop STS, ONE __syncthreads per K-tile.
// ---------------------------------------------------------------------------
#define GBK    16
#define GSPLIT 12
#define GPAD   132
#define GEMM_SMEM (2 * 2 * GBK * GPAD * (int)sizeof(float))   // 67584 B

__global__ __launch_bounds__(256, 2) void gemm_nt_kernel(
    const float* __restrict__ A, const float* __restrict__ B,
    float* __restrict__ C, int M, int N, int K)
{
    extern __shared__ float gsm[];
    float* Asm = gsm;                        // [2][GBK][GPAD]
    float* Bsm = gsm + 2 * GBK * GPAD;       // [2][GBK][GPAD]

    const int tid  = threadIdx.x;
    const int lane = tid & 31;
    const int warp = tid >> 5;
    // square warp tile: 8 tx x 4 ty per warp (bijective over 16x16 grid)
    const int tx = (lane & 7)  | ((warp & 1) << 3);
    const int ty = (lane >> 3) | ((warp >> 1) << 2);
    const int bm = blockIdx.y * 128;
    const int bn = blockIdx.x * 128;

    const int lc = tid & 15;          // k within tile (loader mapping)
    const int lr = (tid >> 4) * 4;    // row base

    // loop-carried base pointers (advance by GBK per tile)
    const float* Ap[2];
    const float* Bp[2];
#pragma unroll
    for (int half = 0; half < 2; half++) {
        Ap[half] = A + (size_t)(bm + lr + half * 64) * K + lc;
        Bp[half] = B + (size_t)(bn + lr + half * 64) * K + lc;
    }

    float ra[2][4], rb[2][4];

    // prefetch tile 0 into registers
#pragma unroll
    for (int half = 0; half < 2; half++)
#pragma unroll
        for (int i = 0; i < 4; i++) {
            ra[half][i] = Ap[half][i * K];
            rb[half][i] = Bp[half][i * K];
        }
    // store to buffer 0
#pragma unroll
    for (int half = 0; half < 2; half++) {
        int r = lr + half * 64;
        *(float4*)&Asm[(0 * GBK + lc) * GPAD + r] =
            make_float4(ra[half][0], ra[half][1], ra[half][2], ra[half][3]);
        *(float4*)&Bsm[(0 * GBK + lc) * GPAD + r] =
            make_float4(rb[half][0], rb[half][1], rb[half][2], rb[half][3]);
    }
    __syncthreads();

    // packed accumulators: acc2[i][j2] = columns (tx*8 + 2*j2, +1)
    unsigned long long acc2[8][4];
#pragma unroll
    for (int i = 0; i < 8; i++)
#pragma unroll
        for (int j = 0; j < 4; j++) acc2[i][j] = 0ULL;

    int cur = 0;
    for (int k0 = 0; k0 < K; k0 += GBK) {
        const bool has_next = (k0 + GBK) < K;

        // prefetch next tile into registers (shadow: first GSPLIT kk below)
        if (has_next) {
#pragma unroll
            for (int half = 0; half < 2; half++) {
                Ap[half] += GBK;
                Bp[half] += GBK;
#pragma unroll
                for (int i = 0; i < 4; i++) {
                    ra[half][i] = Ap[half][i * K];
                    rb[half][i] = Bp[half][i * K];
                }
            }
        }

        const float* Ac = &Asm[cur * GBK * GPAD];
        const float* Bc = &Bsm[cur * GBK * GPAD];

        // compute kk = 0 .. GSPLIT-1 (packed f32x2)
#pragma unroll
        for (int kk = 0; kk < GSPLIT; kk++) {
            float a[8];
            *(float4*)&a[0] = *(const float4*)&Ac[kk * GPAD + ty * 8];
            *(float4*)&a[4] = *(const float4*)&Ac[kk * GPAD + ty * 8 + 4];
            ulonglong2 b01 = *(const ulonglong2*)&Bc[kk * GPAD + tx * 8];
            ulonglong2 b23 = *(const ulonglong2*)&Bc[kk * GPAD + tx * 8 + 4];
            unsigned long long b2[4] = {b01.x, b01.y, b23.x, b23.y};
#pragma unroll
            for (int i = 0; i < 8; i++) {
                unsigned long long a2 = dup2(a[i]);   // alu pipe, dual-issues
#pragma unroll
                for (int j = 0; j < 4; j++)
                    acc2[i][j] = fma2(a2, b2[j], acc2[i][j]);
            }
        }

        // stage next tile mid-loop: remaining kk absorb STS + barrier drain
        if (has_next) {
            int nxt = cur ^ 1;
#pragma unroll
            for (int half = 0; half < 2; half++) {
                int r = lr + half * 64;
                *(float4*)&Asm[(nxt * GBK + lc) * GPAD + r] =
                    make_float4(ra[half][0], ra[half][1], ra[half][2], ra[half][3]);
                *(float4*)&Bsm[(nxt * GBK + lc) * GPAD + r] =
                    make_float4(rb[half][0], rb[half][1], rb[half][2], rb[half][3]);
            }
        }

        // compute kk = GSPLIT .. GBK-1
#pragma unroll
        for (int kk = GSPLIT; kk < GBK; kk++) {
            float a[8];
            *(float4*)&a[0] = *(const float4*)&Ac[kk * GPAD + ty * 8];
            *(float4*)&a[4] = *(const float4*)&Ac[kk * GPAD + ty * 8 + 4];
            ulonglong2 b01 = *(const ulonglong2*)&Bc[kk * GPAD + tx * 8];
            ulonglong2 b23 = *(const ulonglong2*)&Bc[kk * GPAD + tx * 8 + 4];
            unsigned long long b2[4] = {b01.x, b01.y, b23.x, b23.y};
#pragma unroll
            for (int i = 0; i < 8; i++) {
                unsigned long long a2 = dup2(a[i]);
#pragma unroll
                for (int j = 0; j < 4; j++)
                    acc2[i][j] = fma2(a2, b2[j], acc2[i][j]);
            }
        }

        __syncthreads();
        cur ^= 1;
    }

    // epilogue: packed pairs are already in float memory order -> store direct
#pragma unroll
    for (int i = 0; i < 8; i++) {
        size_t base = (size_t)(bm + ty * 8 + i) * N + bn + tx * 8;
        ulonglong2 lo, hi;
        lo.x = acc2[i][0]; lo.y = acc2[i][1];
        hi.x = acc2[i][2]; hi.y = acc2[i][3];
        *(ulonglong2*)&C[base]     = lo;
        *(ulonglong2*)&C[base + 4] = hi;
    }
}

// ---------------------------------------------------------------------------
// Flash attention (causal, fp32, packed f32x2, log2-domain softmax).
// BQ=BK=64, hd=64, 256 threads, 4x4 microtile. (Lane mapping UNCHANGED:
// the width-16 shuffle reductions require a row's 16 tx owners in-warp;
// no flash profile exists yet, so no blind edits here.)
// LPT grid order; K/V double-buffered, one barrier/tile; hoisted STS.
// ---------------------------------------------------------------------------
#define FPITCH 68
#define FTILE  (64 * FPITCH)                                  // 4352 floats
#define FLASH_SMEM (6 * FTILE * (int)sizeof(float))           // 104448 B
// (1/sqrt(64)) * log2(e) = 0.125 * 1.4426950408889634
#define QSCALE 0.18033688011111793f
#define TILESTEP (64 * ROWSTR)

__global__ __launch_bounds__(256, 2) void flash_attn_kernel(
    const float* __restrict__ qkv, float* __restrict__ outp)
{
    extern __shared__ float sm[];
    float* Qt = sm;                              // [64 hd][68] transposed, prescaled
    // buf b: Kt = sm + (1+2b)*FTILE, Vs = sm + (2+2b)*FTILE
    float* Ss = sm + 5 * FTILE;                  // [64 q][68] probabilities

    const int tid = threadIdx.x;
    const int tx = tid & 15;
    const int ty = tid >> 4;
    // LPT order: x = (b,h); y = q-block, reversed so heavy rows launch first
    const int q0 = (gridDim.y - 1 - blockIdx.y) * 64;
    const int b  = blockIdx.x >> 4;
    const int h  = blockIdx.x & 15;

    const size_t seqbase = (size_t)b * L_SEQ * ROWSTR;

    const int c  = tid & 63;          // hd column for K/Q transpose loads
    const int r4 = (tid >> 6) * 4;    // row base
    const int vr = ty;                // V row base
    const int vc = tx * 4;            // V col base

    // loop-carried per-thread base pointers (advance by TILESTEP per tile)
    const float* Qp = qkv + seqbase + h * HDIM + c + (size_t)q0 * ROWSTR;
    const float* Kp = qkv + seqbase + D_MODEL + h * HDIM + c;
    const float* Vp = qkv + seqbase + 2 * D_MODEL + h * HDIM + vc;
    int koff[4], voff[4];
#pragma unroll
    for (int it = 0; it < 4; it++) {
        koff[it] = (r4 + it * 16) * ROWSTR;
        voff[it] = (vr + it * 16) * ROWSTR;
    }

    const int n_tiles = q0 / 64 + 1;

    float kreg[4][4];
    float4 vreg[4];

    // ---- prologue: Q (prescaled to log2 domain) + first K/V tile ----
#pragma unroll
    for (int it = 0; it < 4; it++) {
        int r = r4 + it * 16;
        float t0 = Qp[koff[it] + 0 * ROWSTR] * QSCALE;
        float t1 = Qp[koff[it] + 1 * ROWSTR] * QSCALE;
        float t2 = Qp[koff[it] + 2 * ROWSTR] * QSCALE;
        float t3 = Qp[koff[it] + 3 * ROWSTR] * QSCALE;
        *(float4*)&Qt[c * FPITCH + r] = make_float4(t0, t1, t2, t3);
    }
#pragma unroll
    for (int it = 0; it < 4; it++) {
        kreg[it][0] = Kp[koff[it] + 0 * ROWSTR];
        kreg[it][1] = Kp[koff[it] + 1 * ROWSTR];
        kreg[it][2] = Kp[koff[it] + 2 * ROWSTR];
        kreg[it][3] = Kp[koff[it] + 3 * ROWSTR];
    }
#pragma unroll
    for (int it = 0; it < 4; it++)
        vreg[it] = *(const float4*)&Vp[voff[it]];

    {
        float* Kt0 = sm + 1 * FTILE;
        float* Vs0 = sm + 2 * FTILE;
#pragma unroll
        for (int it = 0; it < 4; it++) {
            int r = r4 + it * 16;
            *(float4*)&Kt0[c * FPITCH + r] =
                make_float4(kreg[it][0], kreg[it][1], kreg[it][2], kreg[it][3]);
        }
#pragma unroll
        for (int it = 0; it < 4; it++)
            *(float4*)&Vs0[(vr + it * 16) * FPITCH + vc] = vreg[it];
    }
    __syncthreads();

    // packed accumulators: acc2[i][j2] = hd cols (tx*4 + 2*j2, +1)
    unsigned long long acc2[4][2];
    float m_i[4], l_i[4];
#pragma unroll
    for (int i = 0; i < 4; i++) {
        m_i[i] = -1e30f;
        l_i[i] = 0.0f;
        acc2[i][0] = 0ULL;
        acc2[i][1] = 0ULL;
    }

    int cur = 0;
    for (int t = 0; t < n_tiles; t++) {
        const bool has_next = (t + 1) < n_tiles;
        const float* Kt = sm + (1 + 2 * cur) * FTILE;
        const float* Vs = sm + (2 + 2 * cur) * FTILE;

        // prefetch NEXT K/V tile into registers (shadow: S-loop + softmax)
        if (has_next) {
            Kp += TILESTEP;
            Vp += TILESTEP;
#pragma unroll
            for (int it = 0; it < 4; it++) {
                kreg[it][0] = Kp[koff[it] + 0 * ROWSTR];
                kreg[it][1] = Kp[koff[it] + 1 * ROWSTR];
                kreg[it][2] = Kp[koff[it] + 2 * ROWSTR];
                kreg[it][3] = Kp[koff[it] + 3 * ROWSTR];
            }
#pragma unroll
            for (int it = 0; it < 4; it++)
                vreg[it] = *(const float4*)&Vp[voff[it]];
        }

        // S = (Q*scale*log2e) K^T  -- packed along k-columns (tx*4 pairs)
        unsigned long long s2[4][2];
#pragma unroll
        for (int i = 0; i < 4; i++) { s2[i][0] = 0ULL; s2[i][1] = 0ULL; }

#pragma unroll
        for (int kk = 0; kk < 64; kk++) {
            float av[4];
            *(float4*)av = *(const float4*)&Qt[kk * FPITCH + ty * 4];
            ulonglong2 kb = *(const ulonglong2*)&Kt[kk * FPITCH + tx * 4];
#pragma unroll
            for (int i = 0; i < 4; i++) {
                unsigned long long a2 = dup2(av[i]);
                s2[i][0] = fma2(a2, kb.x, s2[i][0]);
                s2[i][1] = fma2(a2, kb.y, s2[i][1]);
            }
        }

        // unpack S for masking/softmax
        float s[4][4];
#pragma unroll
        for (int i = 0; i < 4; i++) {
            unpack2(s2[i][0], s[i][0], s[i][1]);
            unpack2(s2[i][1], s[i][2], s[i][3]);
        }

        // causal mask on the diagonal tile (last tile: k0 == q0)
        if (!has_next) {
#pragma unroll
            for (int i = 0; i < 4; i++) {
                int qi = ty * 4 + i;
#pragma unroll
                for (int j = 0; j < 4; j++) {
                    int kj = tx * 4 + j;
                    if (kj > qi) s[i][j] = -1e30f;
                }
            }
        }

        // ---- online softmax, log2 domain, STAGE-MAJOR (4 rows interleaved) --
        float mx[4], rs[4], mnew[4], sf[4];
#pragma unroll
        for (int i = 0; i < 4; i++)
            mx[i] = fmaxf(fmaxf(s[i][0], s[i][1]), fmaxf(s[i][2], s[i][3]));
#pragma unroll
        for (int off = 8; off >= 1; off >>= 1)
#pragma unroll
            for (int i = 0; i < 4; i++)
                mx[i] = fmaxf(mx[i], __shfl_xor_sync(0xffffffffu, mx[i], off, 16));
#pragma unroll
        for (int i = 0; i < 4; i++) {
            mnew[i] = fmaxf(m_i[i], mx[i]);
            sf[i]   = ex2(m_i[i] - mnew[i]);
        }
#pragma unroll
        for (int i = 0; i < 4; i++) {
            s[i][0] = ex2(s[i][0] - mnew[i]);
            s[i][1] = ex2(s[i][1] - mnew[i]);
            s[i][2] = ex2(s[i][2] - mnew[i]);
            s[i][3] = ex2(s[i][3] - mnew[i]);
            rs[i] = (s[i][0] + s[i][1]) + (s[i][2] + s[i][3]);
        }

        // Ss STS hoisted: s[] is final; STS->LDS chain covered by shuffles
#pragma unroll
        for (int i = 0; i < 4; i++)
            *(float4*)&Ss[(ty * 4 + i) * FPITCH + tx * 4] =
                make_float4(s[i][0], s[i][1], s[i][2], s[i][3]);

#pragma unroll
        for (int off = 8; off >= 1; off >>= 1)
#pragma unroll
            for (int i = 0; i < 4; i++)
                rs[i] += __shfl_xor_sync(0xffffffffu, rs[i], off, 16);
#pragma unroll
        for (int i = 0; i < 4; i++) {
            l_i[i] = l_i[i] * sf[i] + rs[i];
            m_i[i] = mnew[i];
            unsigned long long sf2 = dup2(sf[i]);
            acc2[i][0] = mul2(acc2[i][0], sf2);
            acc2[i][1] = mul2(acc2[i][1], sf2);
        }
        __syncwarp();

        // K/V staging STS hoisted BEFORE P.V (targets buf[nxt], disjoint)
        if (has_next) {
            int nxt = cur ^ 1;
            float* Ktn = sm + (1 + 2 * nxt) * FTILE;
            float* Vsn = sm + (2 + 2 * nxt) * FTILE;
#pragma unroll
            for (int it = 0; it < 4; it++) {
                int r = r4 + it * 16;
                *(float4*)&Ktn[c * FPITCH + r] =
                    make_float4(kreg[it][0], kreg[it][1], kreg[it][2], kreg[it][3]);
            }
#pragma unroll
            for (int it = 0; it < 4; it++)
                *(float4*)&Vsn[(vr + it * 16) * FPITCH + vc] = vreg[it];
        }

        // O += P V  -- packed along hd columns
#pragma unroll
        for (int kk4 = 0; kk4 < 64; kk4 += 4) {
            float4 p[4];
#pragma unroll
            for (int i = 0; i < 4; i++)
                p[i] = *(const float4*)&Ss[(ty * 4 + i) * FPITCH + kk4];
#pragma unroll
            for (int u = 0; u < 4; u++) {
                ulonglong2 v2 = *(const ulonglong2*)&Vs[(kk4 + u) * FPITCH + tx * 4];
                float pe[4];
                pe[0] = (u == 0) ? p[0].x : (u == 1) ? p[0].y : (u == 2) ? p[0].z : p[0].w;
                pe[1] = (u == 0) ? p[1].x : (u == 1) ? p[1].y : (u == 2) ? p[1].z : p[1].w;
                pe[2] = (u == 0) ? p[2].x : (u == 1) ? p[2].y : (u == 2) ? p[2].z : p[2].w;
                pe[3] = (u == 0) ? p[3].x : (u == 1) ? p[3].y : (u == 2) ? p[3].z : p[3].w;
#pragma unroll
                for (int i = 0; i < 4; i++) {
                    unsigned long long pd = dup2(pe[i]);
                    acc2[i][0] = fma2(pd, v2.x, acc2[i][0]);
                    acc2[i][1] = fma2(pd, v2.y, acc2[i][1]);
                }
            }
        }

        // single barrier per tile: publishes buf[nxt] for iteration t+1
        if (has_next) {
            __syncthreads();
            cur ^= 1;
        }
    }

    // epilogue: O *= 1/l (packed), store packed pairs directly
#pragma unroll
    for (int i = 0; i < 4; i++) {
        unsigned long long inv2 = dup2(frcp(l_i[i]));
        ulonglong2 o;
        o.x = mul2(acc2[i][0], inv2);
        o.y = mul2(acc2[i][1], inv2);
        int q = q0 + ty * 4 + i;
        size_t base = (size_t)(b * L_SEQ + q) * D_MODEL + h * HDIM + tx * 4;
        *(ulonglong2*)&outp[base] = o;
    }
}

// ---------------------------------------------------------------------------
extern "C" void kernel_launch(void* const* d_in, const int* in_sizes, int n_in,
                              void* d_out, int out_size)
{
    const float* x     = (const float*)d_in[0];  // [2,2048,1024]
    const float* w_qkv = (const float*)d_in[1];  // [3072,1024]
    const float* w_out = (const float*)d_in[2];  // [1024,1024]
    float* out = (float*)d_out;                  // [2,2048,1024]

    float *qkv_buf = nullptr, *att_buf = nullptr;
    cudaGetSymbolAddress((void**)&qkv_buf, g_qkv);
    cudaGetSymbolAddress((void**)&att_buf, g_att);

    cudaFuncSetAttribute(gemm_nt_kernel,
                         cudaFuncAttributeMaxDynamicSharedMemorySize, GEMM_SMEM);
    cudaFuncSetAttribute(flash_attn_kernel,
                         cudaFuncAttributeMaxDynamicSharedMemorySize, FLASH_SMEM);

    const int M = NB * L_SEQ;   // 4096

    // 1) qkv = x @ w_qkv^T   [4096, 3072]
    gemm_nt_kernel<<<dim3(3 * D_MODEL / 128, M / 128), 256, GEMM_SMEM>>>(
        x, w_qkv, qkv_buf, M, 3 * D_MODEL, D_MODEL);

    // 2) causal flash attention -> g_att [4096, 1024]
    //    LPT grid: x = (b,h), y = q-blocks (reversed inside the kernel)
    flash_attn_kernel<<<dim3(NB * NH, L_SEQ / 64), 256, FLASH_SMEM>>>(
        qkv_buf, att_buf);

    // 3) out = att @ w_out^T  [4096, 1024]
    gemm_nt_kernel<<<dim3(D_MODEL / 128, M / 128), 256, GEMM_SMEM>>>(
        att_buf, w_out, out, M, D_MODEL, D_MODEL);
}